// round 12
// baseline (speedup 1.0000x reference)
#include <cuda_runtime.h>
#include <cuda_fp16.h>
#include <cstdint>

#define HDIM 128
#define MAX_NODES 50000
#define MAX_EDGES 800000

// ---------------- device scratch ----------------
__device__ float  g_agg [(size_t)MAX_NODES * HDIM];
__device__ __half g_aggh[(size_t)MAX_NODES * HDIM];
__device__ __half g_xh  [(size_t)MAX_NODES * HDIM];
__device__ __half g_eh  [(size_t)MAX_EDGES * HDIM];
__device__ __half g_W1h [HDIM * 384];   // edge W1^T [n][k] fp16
__device__ __half g_W2h [HDIM * HDIM];
__device__ __half g_Wn1h[HDIM * 256];
__device__ __half g_Wn2h[HDIM * HDIM];

// ---------------- asm helpers ----------------
__device__ __forceinline__ void ldmat4(uint32_t r[4], uint32_t addr) {
    asm volatile("ldmatrix.sync.aligned.m8n8.x4.shared.b16 {%0,%1,%2,%3}, [%4];"
                 : "=r"(r[0]), "=r"(r[1]), "=r"(r[2]), "=r"(r[3]) : "r"(addr));
}
__device__ __forceinline__ void mma16816(float c[4], const uint32_t a[4],
                                         uint32_t b0, uint32_t b1) {
    asm volatile("mma.sync.aligned.m16n8k16.row.col.f32.f16.f16.f32 "
                 "{%0,%1,%2,%3},{%4,%5,%6,%7},{%8,%9},{%0,%1,%2,%3};"
                 : "+f"(c[0]), "+f"(c[1]), "+f"(c[2]), "+f"(c[3])
                 : "r"(a[0]), "r"(a[1]), "r"(a[2]), "r"(a[3]), "r"(b0), "r"(b1));
}
#define CP16(dst, src) \
    asm volatile("cp.async.ca.shared.global [%0], [%1], 16;" :: "r"(dst), "l"(src))
#define CPCOMMIT() asm volatile("cp.async.commit_group;")
#define CPWAIT1()  asm volatile("cp.async.wait_group 1;")

// ---------------- smem layout (bytes) ----------------
// slab pool: 6 x 16KB (128 rows x 64 halfs, 128B rows, XOR-swizzled)
#define IDXO 98304
#define B1O  99328
#define B2O  99840
#define SMEM_BYTES 100352   // 2 CTAs/SM

#define NT 512   // 16 warps, warp grid 4x4, warp tile 32x32

// MODE 0: edge MLP (A = x[src]||x[dst]||eattr_h, K1=384, red-scatter to g_agg)
// MODE 1: node MLP (A = x||agg_h, K1=256, store to out)
template <int MODE, int K1>
__global__ __launch_bounds__(NT, 2)
void gnn_h_kernel(const __half* __restrict__ xh,
                  const int* __restrict__ ei,
                  const __half* __restrict__ xtra,
                  const __half* __restrict__ W1h, const float* __restrict__ b1,
                  const __half* __restrict__ W2h, const float* __restrict__ b2,
                  float* __restrict__ out, int nrows, int E)
{
    extern __shared__ char smem[];
    const uint32_t su = (uint32_t)__cvta_generic_to_shared(smem);
    const int tid = threadIdx.x, lane = tid & 31, wid = tid >> 5;
    const int wm = wid >> 2, wn = wid & 3;        // 4x4 warp grid
    const int base = blockIdx.x * 128;

    int*   sidx = (int*)(smem + IDXO);
    float* b1s  = (float*)(smem + B1O);
    float* b2s  = (float*)(smem + B2O);

    if (tid < 128) {
        b1s[tid] = b1[tid];
        b2s[tid] = b2[tid];
        if (MODE == 0) {
            int e = base + tid; if (e >= nrows) e = nrows - 1;
            sidx[tid]       = ei[e];
            sidx[128 + tid] = ei[E + e];
        }
    }
    __syncthreads();

    // loader coords: row r (0..127), 32B quarter q (0..3)
    const int r = tid >> 2, q = tid & 3;
    int lr = base + r; if (lr >= nrows) lr = nrows - 1;
    const __half* asrc[3];
    if (MODE == 0) {
        asrc[0] = xh + (size_t)sidx[r] * HDIM;
        asrc[1] = xh + (size_t)sidx[128 + r] * HDIM;
        asrc[2] = xtra + (size_t)lr * HDIM;
    } else {
        asrc[0] = xh + (size_t)lr * HDIM;
        asrc[1] = xtra + (size_t)lr * HDIM;
        asrc[2] = nullptr;
    }

    const int NCH1 = K1 / 64;
    const int NTOT = NCH1 + 2;
    const int B2S  = (2 * NCH1 - 6) % 6;   // GEMM2 B slabs: B2S, B2S+1
    const int HS   = B2S + 2;              // hidden slabs:  HS, HS+1
    const int rsw = r & 7;

    auto prefetch1 = [&](int c) {
        const int sa = (2 * c) % 6, sb = (2 * c + 1) % 6;
        {   // weights
            const char* s = (const char*)(W1h + (size_t)r * K1 + c * 64) + q * 32;
            uint32_t d = su + sb * 16384 + r * 128;
            #pragma unroll
            for (int i = 0; i < 2; ++i)
                CP16(d + (((uint32_t)(q * 2 + i) ^ rsw) << 4), s + i * 16);
        }
        {   // A gather
            const char* s = (const char*)(asrc[c >> 1] + (c & 1) * 64) + q * 32;
            uint32_t d = su + sa * 16384 + r * 128;
            #pragma unroll
            for (int i = 0; i < 2; ++i)
                CP16(d + (((uint32_t)(q * 2 + i) ^ rsw) << 4), s + i * 16);
        }
    };
    auto prefetchB2 = [&]() {
        #pragma unroll
        for (int j = 0; j < 2; ++j) {
            const char* s = (const char*)(W2h + (size_t)r * HDIM + j * 64) + q * 32;
            uint32_t d = su + (B2S + j) * 16384 + r * 128;
            #pragma unroll
            for (int i = 0; i < 2; ++i)
                CP16(d + (((uint32_t)(q * 2 + i) ^ rsw) << 4), s + i * 16);
        }
    };

    // ---- mma fragment addressing (warp tile 32x32) ----
    uint32_t aoff[2], asw[2];
    {
        int ra = wm * 32 + (lane & 15);
        aoff[0] = ra * 128;        asw[0] = ra & 7;
        aoff[1] = (ra + 16) * 128; asw[1] = (ra + 16) & 7;
    }
    const uint32_t aub = lane >> 4;
    uint32_t boff[2], bsw[2];
    {
        int nb0 = wn * 32 + ((lane >> 4) << 3) + (lane & 7);
        #pragma unroll
        for (int p = 0; p < 2; ++p) {
            int nb = nb0 + p * 16;
            boff[p] = nb * 128; bsw[p] = nb & 7;
        }
    }
    const uint32_t bub = (lane >> 3) & 1;

    const int mrow = wm * 32 + (lane >> 2);
    const int ncol = wn * 32 + (lane & 3) * 2;
    float acc[2][4][4];
    #pragma unroll
    for (int mt = 0; mt < 2; ++mt)
        #pragma unroll
        for (int nt = 0; nt < 4; ++nt) {
            int n = ncol + nt * 8;
            acc[mt][nt][0] = b1s[n]; acc[mt][nt][1] = b1s[n + 1];
            acc[mt][nt][2] = b1s[n]; acc[mt][nt][3] = b1s[n + 1];
        }

    prefetch1(0); CPCOMMIT();
    prefetch1(1); CPCOMMIT();

    #pragma unroll 1
    for (int c = 0; c < NTOT; ++c) {
        CPWAIT1();
        __syncthreads();
        {
            const int t = c + 2;
            if (t < NCH1)       { prefetch1(t); CPCOMMIT(); }
            else if (t == NCH1) { prefetchB2(); CPCOMMIT(); }
            else if (c < NTOT - 1) { CPCOMMIT(); }   // empty group keeps invariant
        }

        if (c == NCH1) {
            // hidden: ReLU -> fp16 -> slab HS+(wn>>1); re-init acc with b2
            #pragma unroll
            for (int mt = 0; mt < 2; ++mt)
                #pragma unroll
                for (int nt = 0; nt < 4; ++nt) {
                    int m = mrow + mt * 16;
                    int n = ncol + nt * 8;
                    int k = n & 63;
                    uint32_t u = (uint32_t)k >> 3;
                    uint32_t bo = (uint32_t)(lane & 3) * 4;
                    __half2 lo = __floats2half2_rn(fmaxf(acc[mt][nt][0], 0.f),
                                                   fmaxf(acc[mt][nt][1], 0.f));
                    __half2 hi = __floats2half2_rn(fmaxf(acc[mt][nt][2], 0.f),
                                                   fmaxf(acc[mt][nt][3], 0.f));
                    char* s0 = smem + (HS + (wn >> 1)) * 16384 + m * 128
                             + ((u ^ (uint32_t)(m & 7)) << 4) + bo;
                    char* s1 = smem + (HS + (wn >> 1)) * 16384 + (m + 8) * 128
                             + ((u ^ (uint32_t)((m + 8) & 7)) << 4) + bo;
                    *(__half2*)s0 = lo;
                    *(__half2*)s1 = hi;
                    acc[mt][nt][0] = b2s[n]; acc[mt][nt][1] = b2s[n + 1];
                    acc[mt][nt][2] = b2s[n]; acc[mt][nt][3] = b2s[n + 1];
                }
            __syncthreads();
        }

        // ---- mma on chunk c ----
        const uint32_t Ab = su + ((c < NCH1) ? ((2 * c) % 6)
                                             : (HS + c - NCH1)) * 16384;
        const uint32_t Bb = su + ((c < NCH1) ? ((2 * c + 1) % 6)
                                             : (B2S + c - NCH1)) * 16384;
        #pragma unroll
        for (int ks = 0; ks < 4; ++ks) {
            const uint32_t ua = aub + ks * 2;
            const uint32_t ub = bub + ks * 2;
            uint32_t a0[4], a1[4], bf[2][4];
            ldmat4(a0, Ab + aoff[0] + ((ua ^ asw[0]) << 4));
            ldmat4(a1, Ab + aoff[1] + ((ua ^ asw[1]) << 4));
            #pragma unroll
            for (int p = 0; p < 2; ++p)
                ldmat4(bf[p], Bb + boff[p] + ((ub ^ bsw[p]) << 4));
            #pragma unroll
            for (int nt = 0; nt < 4; ++nt) {
                mma16816(acc[0][nt], a0, bf[nt >> 1][(nt & 1) * 2], bf[nt >> 1][(nt & 1) * 2 + 1]);
                mma16816(acc[1][nt], a1, bf[nt >> 1][(nt & 1) * 2], bf[nt >> 1][(nt & 1) * 2 + 1]);
            }
        }
    }
    __syncthreads();   // all mma done before staging overwrites slabs

    // ---- epilogue: stage fp32, then scatter/store ----
    float* stg = (float*)smem;   // [128][132]
    #pragma unroll
    for (int mt = 0; mt < 2; ++mt)
        #pragma unroll
        for (int nt = 0; nt < 4; ++nt) {
            int m = mrow + mt * 16;
            int n = ncol + nt * 8;
            *(float2*)(stg + m * 132 + n)       = make_float2(acc[mt][nt][0], acc[mt][nt][1]);
            *(float2*)(stg + (m + 8) * 132 + n) = make_float2(acc[mt][nt][2], acc[mt][nt][3]);
        }
    __syncthreads();

    {
        const int row = tid >> 2, qq = tid & 3;
        if (base + row < nrows) {
            const float* s = stg + row * 132 + qq * 32;
            if (MODE == 0) {
                const int cd = sidx[128 + row];
                float* dst = g_agg + (size_t)cd * HDIM + qq * 32;
                #pragma unroll
                for (int i = 0; i < 8; ++i) {
                    float4 v = ((const float4*)s)[i];
                    asm volatile("red.global.add.v4.f32 [%0], {%1,%2,%3,%4};"
                                 :: "l"(dst + i * 4), "f"(v.x), "f"(v.y),
                                    "f"(v.z), "f"(v.w) : "memory");
                }
            } else {
                float4* dst = (float4*)(out + (size_t)(base + row) * HDIM + qq * 32);
                #pragma unroll
                for (int i = 0; i < 8; ++i)
                    dst[i] = ((const float4*)s)[i];
            }
        }
    }
}

// weight prep: dst[n*K+k] = half(src[k*128+n])
__global__ void prep_w_h(__half* dst, const float* src, int K) {
    int i = blockIdx.x * 256 + threadIdx.x;
    if (i < K * HDIM) {
        int k = i / HDIM, n = i % HDIM;
        dst[(size_t)n * K + k] = __float2half(src[(size_t)k * HDIM + n]);
    }
}
__global__ void conv_h8_2(__half* __restrict__ d0, const float* __restrict__ s0,
                          size_t n8_0,
                          __half* __restrict__ d1, const float* __restrict__ s1,
                          size_t n8_1) {
    size_t i = (size_t)blockIdx.x * 256 + threadIdx.x;
    const float* src; __half* dst; size_t j;
    if (i < n8_0)            { src = s0; dst = d0; j = i; }
    else if (i < n8_0 + n8_1){ src = s1; dst = d1; j = i - n8_0; }
    else return;
    float4 v0 = ((const float4*)src)[j * 2];
    float4 v1 = ((const float4*)src)[j * 2 + 1];
    __half2 hh[4] = { __floats2half2_rn(v0.x, v0.y), __floats2half2_rn(v0.z, v0.w),
                      __floats2half2_rn(v1.x, v1.y), __floats2half2_rn(v1.z, v1.w) };
    *(uint4*)(dst + j * 8) = *(const uint4*)hh;
}
__global__ void conv_h8(__half* __restrict__ dst, const float* __restrict__ src,
                        size_t n8) {
    size_t i = (size_t)blockIdx.x * 256 + threadIdx.x;
    if (i < n8) {
        float4 v0 = ((const float4*)src)[i * 2];
        float4 v1 = ((const float4*)src)[i * 2 + 1];
        __half2 hh[4] = { __floats2half2_rn(v0.x, v0.y), __floats2half2_rn(v0.z, v0.w),
                          __floats2half2_rn(v1.x, v1.y), __floats2half2_rn(v1.z, v1.w) };
        *(uint4*)(dst + i * 8) = *(const uint4*)hh;
    }
}

extern "C" void kernel_launch(void* const* d_in, const int* in_sizes, int n_in,
                              void* d_out, int out_size)
{
    const float* x     = (const float*)d_in[0];
    const int*   ei    = (const int*)d_in[1];
    const float* eattr = (const float*)d_in[2];
    const float* We1   = (const float*)d_in[3];
    const float* be1   = (const float*)d_in[4];
    const float* We2   = (const float*)d_in[5];
    const float* be2   = (const float*)d_in[6];
    const float* Wn1   = (const float*)d_in[7];
    const float* bn1   = (const float*)d_in[8];
    const float* Wn2   = (const float*)d_in[9];
    const float* bn2   = (const float*)d_in[10];
    float* out = (float*)d_out;

    const int N = in_sizes[0] / HDIM;   // 50000
    const int E = in_sizes[1] / 2;      // 800000

    cudaFuncSetAttribute(gnn_h_kernel<0, 384>,
                         cudaFuncAttributeMaxDynamicSharedMemorySize, SMEM_BYTES);
    cudaFuncSetAttribute(gnn_h_kernel<1, 256>,
                         cudaFuncAttributeMaxDynamicSharedMemorySize, SMEM_BYTES);

    void *aggp, *agghp, *xhp, *ehp, *w1, *w2, *wn1, *wn2;
    cudaGetSymbolAddress(&aggp,  g_agg);
    cudaGetSymbolAddress(&agghp, g_aggh);
    cudaGetSymbolAddress(&xhp,   g_xh);
    cudaGetSymbolAddress(&ehp,   g_eh);
    cudaGetSymbolAddress(&w1,    g_W1h);
    cudaGetSymbolAddress(&w2,    g_W2h);
    cudaGetSymbolAddress(&wn1,   g_Wn1h);
    cudaGetSymbolAddress(&wn2,   g_Wn2h);

    cudaMemsetAsync(aggp, 0, (size_t)N * HDIM * sizeof(float), 0);

    prep_w_h<<<(384 * HDIM + 255) / 256, 256>>>((__half*)w1,  We1, 384);
    prep_w_h<<<(HDIM * HDIM + 255) / 256, 256>>>((__half*)w2,  We2, HDIM);
    prep_w_h<<<(256 * HDIM + 255) / 256, 256>>>((__half*)wn1, Wn1, 256);
    prep_w_h<<<(HDIM * HDIM + 255) / 256, 256>>>((__half*)wn2, Wn2, HDIM);

    const size_t nx8 = (size_t)N * HDIM / 8;
    const size_t ne8 = (size_t)E * HDIM / 8;
    conv_h8_2<<<(unsigned)((nx8 + ne8 + 255) / 256), 256>>>(
        (__half*)xhp, x, nx8, (__half*)ehp, eattr, ne8);

    gnn_h_kernel<0, 384><<<(E + 127) / 128, NT, SMEM_BYTES>>>(
        (const __half*)xhp, ei, (const __half*)ehp,
        (const __half*)w1, be1, (const __half*)w2, be2, nullptr, E, E);

    conv_h8<<<(unsigned)((nx8 + 255) / 256), 256>>>((__half*)agghp,
                                                    (const float*)aggp, nx8);

    gnn_h_kernel<1, 256><<<(N + 127) / 128, NT, SMEM_BYTES>>>(
        (const __half*)xhp, nullptr, (const __half*)agghp,
        (const __half*)wn1, bn1, (const __half*)wn2, bn2, out, N, 0);
}

// round 13
// speedup vs baseline: 1.0204x; 1.0204x over previous
#include <cuda_runtime.h>
#include <cuda_fp16.h>
#include <cstdint>

#define HDIM 128
#define MAX_NODES 50000

// ---------------- device scratch ----------------
__device__ float  g_agg [(size_t)MAX_NODES * HDIM];
__device__ __half g_xh  [(size_t)MAX_NODES * HDIM];
__device__ __half g_W1h [HDIM * 384];   // edge W1^T [n][k] fp16
__device__ __half g_W2h [HDIM * HDIM];
__device__ __half g_Wn1h[HDIM * 256];
__device__ __half g_Wn2h[HDIM * HDIM];

// ---------------- asm helpers ----------------
__device__ __forceinline__ void ldmat4(uint32_t r[4], uint32_t addr) {
    asm volatile("ldmatrix.sync.aligned.m8n8.x4.shared.b16 {%0,%1,%2,%3}, [%4];"
                 : "=r"(r[0]), "=r"(r[1]), "=r"(r[2]), "=r"(r[3]) : "r"(addr));
}
__device__ __forceinline__ void mma16816(float c[4], const uint32_t a[4],
                                         uint32_t b0, uint32_t b1) {
    asm volatile("mma.sync.aligned.m16n8k16.row.col.f32.f16.f16.f32 "
                 "{%0,%1,%2,%3},{%4,%5,%6,%7},{%8,%9},{%0,%1,%2,%3};"
                 : "+f"(c[0]), "+f"(c[1]), "+f"(c[2]), "+f"(c[3])
                 : "r"(a[0]), "r"(a[1]), "r"(a[2]), "r"(a[3]), "r"(b0), "r"(b1));
}
#define CP16(dst, src) \
    asm volatile("cp.async.ca.shared.global [%0], [%1], 16;" :: "r"(dst), "l"(src))
#define CPCOMMIT() asm volatile("cp.async.commit_group;")
#define CPWAIT0()  asm volatile("cp.async.wait_group 0;")

// ---------------- smem layout (bytes) ----------------
// A0/A1, B0/B1, H0/H1: 128 rows x 64 halfs (128B rows, XOR-swizzled), 16KB each
// H region (32KB) doubles as fp32 staging for the trailing fp32 chunks,
// one chunk at a time (convert serializes before the next staging prefetch).
#define AOFF 0
#define BOFF 32768
#define HOFF 65536
#define IDXO 98304
#define B1O  99328
#define B2O  99840
#define SMEM_BYTES 100352   // 2 CTAs/SM

// chunk layout (original order, NO reorder):
// MODE 0 (K1=384): c0,1 = x[src]; c2,3 = x[dst] (fp16); c4,5 = eattr (fp32 staged)
// MODE 1 (K1=256): c0,1 = x (fp16); c2,3 = agg (fp32 staged)
template <int MODE, int K1>
__global__ __launch_bounds__(256, 2)
void gnn_h_kernel(const __half* __restrict__ xh,
                  const int* __restrict__ ei,
                  const float* __restrict__ fextra,   // eattr (MODE0) / g_agg (MODE1)
                  const __half* __restrict__ W1h, const float* __restrict__ b1,
                  const __half* __restrict__ W2h, const float* __restrict__ b2,
                  float* __restrict__ out, int nrows, int E)
{
    extern __shared__ char smem[];
    const uint32_t su = (uint32_t)__cvta_generic_to_shared(smem);
    const int tid = threadIdx.x, lane = tid & 31, wid = tid >> 5;
    const int wm = wid >> 1, wn = wid & 1;
    const int base = blockIdx.x * 128;

    int*   sidx = (int*)(smem + IDXO);
    float* b1s  = (float*)(smem + B1O);
    float* b2s  = (float*)(smem + B2O);

    if (tid < 128) {
        b1s[tid] = b1[tid];
        b2s[tid] = b2[tid];
        if (MODE == 0) {
            int e = base + tid; if (e >= nrows) e = nrows - 1;
            sidx[tid]       = ei[e];
            sidx[128 + tid] = ei[E + e];
        }
    }
    __syncthreads();

    // loader coords: row r (0..127), half h (64B of the 128B fp16 row)
    const int r = tid >> 1, h = tid & 1;
    int lr = base + r; if (lr >= nrows) lr = nrows - 1;
    const __half* asrc[2];
    if (MODE == 0) {
        asrc[0] = xh + (size_t)sidx[r] * HDIM;
        asrc[1] = xh + (size_t)sidx[128 + r] * HDIM;
    } else {
        asrc[0] = xh + (size_t)lr * HDIM;
        asrc[1] = nullptr;
    }
    const float* frow = fextra + (size_t)lr * HDIM;

    const int NCH1 = K1 / 64;
    const int NTOT = NCH1 + 2;
    const int F0   = NCH1 - 2;          // first fp32 chunk
    const int rsw = r & 7;

    // ---- prefetch chunk c ----
    auto prefetch = [&](int c) {
        {   // B chunk (weights)
            const __half* W; int Ks, ko;
            if (c < NCH1) { W = W1h; Ks = K1; ko = c * 64; }
            else          { W = W2h; Ks = HDIM; ko = (c - NCH1) * 64; }
            const char* s = (const char*)(W + (size_t)r * Ks + ko) + h * 64;
            uint32_t d = su + BOFF + (c & 1) * 16384 + r * 128;
            #pragma unroll
            for (int i = 0; i < 4; ++i)
                CP16(d + (((uint32_t)(h * 4 + i) ^ rsw) << 4), s + i * 16);
        }
        if (c < F0) {          // fp16 gather chunk
            const char* s = (const char*)(asrc[c >> 1] + (c & 1) * 64) + h * 64;
            uint32_t d = su + AOFF + (c & 1) * 16384 + r * 128;
            #pragma unroll
            for (int i = 0; i < 4; ++i)
                CP16(d + (((uint32_t)(h * 4 + i) ^ rsw) << 4), s + i * 16);
        } else if (c < NCH1) { // fp32 chunk -> raw staging (full 32KB H region)
            const char* s = (const char*)(frow + (c & 1) * 64) + h * 128;
            uint32_t d = su + HOFF + r * 256 + h * 128;
            #pragma unroll
            for (int i = 0; i < 8; ++i)
                CP16(d + i * 16, s + i * 16);
        }
    };

    // ---- mma fragment addressing ----
    uint32_t aoff[2], asw[2];
    {
        int ra = wm * 32 + (lane & 15);
        aoff[0] = ra * 128;        asw[0] = ra & 7;
        aoff[1] = (ra + 16) * 128; asw[1] = (ra + 16) & 7;
    }
    const uint32_t aub = lane >> 4;
    uint32_t boff[4], bsw[4];
    {
        int nb0 = wn * 64 + ((lane >> 4) << 3) + (lane & 7);
        #pragma unroll
        for (int p = 0; p < 4; ++p) {
            int nb = nb0 + p * 16;
            boff[p] = nb * 128; bsw[p] = nb & 7;
        }
    }
    const uint32_t bub = (lane >> 3) & 1;

    const int mrow = wm * 32 + (lane >> 2);
    const int ncol = wn * 64 + (lane & 3) * 2;
    float acc[2][8][4];
    #pragma unroll
    for (int mt = 0; mt < 2; ++mt)
        #pragma unroll
        for (int nt = 0; nt < 8; ++nt) {
            int n = ncol + nt * 8;
            acc[mt][nt][0] = b1s[n]; acc[mt][nt][1] = b1s[n + 1];
            acc[mt][nt][2] = b1s[n]; acc[mt][nt][3] = b1s[n + 1];
        }

    prefetch(0); CPCOMMIT();

    #pragma unroll 1
    for (int c = 0; c < NTOT; ++c) {
        CPWAIT0();
        __syncthreads();

        if (c >= F0 && c < NCH1) {
            // convert fp32 staging (128x64 linear) -> A slab (c&1), swizzled fp16
            const int slab = (c & 1) * 16384;
            #pragma unroll
            for (int j = 0; j < 8; ++j) {
                float4 v = *(const float4*)(smem + HOFF + j * 4096 + tid * 16);
                int row = j * 16 + wid * 2 + (lane >> 4);
                uint32_t u = ((uint32_t)(lane & 15)) >> 1;
                char* p = smem + AOFF + slab + row * 128
                        + ((u ^ (uint32_t)(row & 7)) << 4) + (lane & 1) * 8;
                ((__half2*)p)[0] = __floats2half2_rn(v.x, v.y);
                ((__half2*)p)[1] = __floats2half2_rn(v.z, v.w);
            }
            __syncthreads();   // staging free + slab ready before next pf / mma
        }

        if (c + 1 < NTOT) { prefetch(c + 1); CPCOMMIT(); }

        if (c == NCH1) {
            // hidden: ReLU -> fp16 -> H slabs (slab = wn); re-init acc with b2
            #pragma unroll
            for (int mt = 0; mt < 2; ++mt)
                #pragma unroll
                for (int nt = 0; nt < 8; ++nt) {
                    int m = mrow + mt * 16;
                    int n = ncol + nt * 8;
                    int k = n & 63;
                    uint32_t u = (uint32_t)k >> 3;
                    uint32_t bo = (uint32_t)(lane & 3) * 4;
                    __half2 lo = __floats2half2_rn(fmaxf(acc[mt][nt][0], 0.f),
                                                   fmaxf(acc[mt][nt][1], 0.f));
                    __half2 hi = __floats2half2_rn(fmaxf(acc[mt][nt][2], 0.f),
                                                   fmaxf(acc[mt][nt][3], 0.f));
                    char* s0 = smem + HOFF + wn * 16384 + m * 128
                             + ((u ^ (uint32_t)(m & 7)) << 4) + bo;
                    char* s1 = smem + HOFF + wn * 16384 + (m + 8) * 128
                             + ((u ^ (uint32_t)((m + 8) & 7)) << 4) + bo;
                    *(__half2*)s0 = lo;
                    *(__half2*)s1 = hi;
                    acc[mt][nt][0] = b2s[n]; acc[mt][nt][1] = b2s[n + 1];
                    acc[mt][nt][2] = b2s[n]; acc[mt][nt][3] = b2s[n + 1];
                }
            __syncthreads();
        }

        // ---- mma on chunk c ----
        const uint32_t Ab = (c < NCH1) ? (su + AOFF + (c & 1) * 16384)
                                       : (su + HOFF + (c - NCH1) * 16384);
        const uint32_t Bb = su + BOFF + (c & 1) * 16384;
        #pragma unroll
        for (int ks = 0; ks < 4; ++ks) {
            const uint32_t ua = aub + ks * 2;
            const uint32_t ub = bub + ks * 2;
            uint32_t a0[4], a1[4], bf[4][4];
            ldmat4(a0, Ab + aoff[0] + ((ua ^ asw[0]) << 4));
            ldmat4(a1, Ab + aoff[1] + ((ua ^ asw[1]) << 4));
            #pragma unroll
            for (int p = 0; p < 4; ++p)
                ldmat4(bf[p], Bb + boff[p] + ((ub ^ bsw[p]) << 4));
            #pragma unroll
            for (int nt = 0; nt < 8; ++nt) {
                mma16816(acc[0][nt], a0, bf[nt >> 1][(nt & 1) * 2], bf[nt >> 1][(nt & 1) * 2 + 1]);
                mma16816(acc[1][nt], a1, bf[nt >> 1][(nt & 1) * 2], bf[nt >> 1][(nt & 1) * 2 + 1]);
            }
        }
        __syncthreads();
    }

    // ---- epilogue: stage fp32, then scatter/store ----
    float* stg = (float*)smem;   // [128][132]
    #pragma unroll
    for (int mt = 0; mt < 2; ++mt)
        #pragma unroll
        for (int nt = 0; nt < 8; ++nt) {
            int m = mrow + mt * 16;
            int n = ncol + nt * 8;
            *(float2*)(stg + m * 132 + n)       = make_float2(acc[mt][nt][0], acc[mt][nt][1]);
            *(float2*)(stg + (m + 8) * 132 + n) = make_float2(acc[mt][nt][2], acc[mt][nt][3]);
        }
    __syncthreads();

    {
        const int row = tid >> 1, hh = tid & 1;
        if (base + row < nrows) {
            const float* s = stg + row * 132 + hh * 64;
            if (MODE == 0) {
                const int cd = sidx[128 + row];
                float* dst = g_agg + (size_t)cd * HDIM + hh * 64;
                #pragma unroll
                for (int i = 0; i < 16; ++i) {
                    float4 v = ((const float4*)s)[i];
                    asm volatile("red.global.add.v4.f32 [%0], {%1,%2,%3,%4};"
                                 :: "l"(dst + i * 4), "f"(v.x), "f"(v.y),
                                    "f"(v.z), "f"(v.w) : "memory");
                }
            } else {
                float4* dst = (float4*)(out + (size_t)(base + row) * HDIM + hh * 64);
                #pragma unroll
                for (int i = 0; i < 16; ++i)
                    dst[i] = ((const float4*)s)[i];
            }
        }
    }
}

// fused weight prep: transpose + fp16 for all 4 matrices
__global__ void prep_all(__half* w1, const float* We1,
                         __half* w2, const float* We2,
                         __half* wn1, const float* Wn1,
                         __half* wn2, const float* Wn2)
{
    int i = blockIdx.x * 256 + threadIdx.x;
    const float* src; __half* dst; int K, j;
    if (i < 49152)      { src = We1; dst = w1;  K = 384; j = i; }
    else if (i < 65536) { src = We2; dst = w2;  K = 128; j = i - 49152; }
    else if (i < 98304) { src = Wn1; dst = wn1; K = 256; j = i - 65536; }
    else if (i < 114688){ src = Wn2; dst = wn2; K = 128; j = i - 98304; }
    else return;
    int k = j / HDIM, n = j % HDIM;
    dst[(size_t)n * K + k] = __float2half(src[(size_t)k * HDIM + n]);
}
// fp32 -> fp16, 8 elems/thread (x only)
__global__ void conv_h8(__half* __restrict__ dst, const float* __restrict__ src,
                        size_t n8) {
    size_t i = (size_t)blockIdx.x * 256 + threadIdx.x;
    if (i < n8) {
        float4 v0 = ((const float4*)src)[i * 2];
        float4 v1 = ((const float4*)src)[i * 2 + 1];
        __half2 hh[4] = { __floats2half2_rn(v0.x, v0.y), __floats2half2_rn(v0.z, v0.w),
                          __floats2half2_rn(v1.x, v1.y), __floats2half2_rn(v1.z, v1.w) };
        *(uint4*)(dst + i * 8) = *(const uint4*)hh;
    }
}

extern "C" void kernel_launch(void* const* d_in, const int* in_sizes, int n_in,
                              void* d_out, int out_size)
{
    const float* x     = (const float*)d_in[0];
    const int*   ei    = (const int*)d_in[1];
    const float* eattr = (const float*)d_in[2];
    const float* We1   = (const float*)d_in[3];
    const float* be1   = (const float*)d_in[4];
    const float* We2   = (const float*)d_in[5];
    const float* be2   = (const float*)d_in[6];
    const float* Wn1   = (const float*)d_in[7];
    const float* bn1   = (const float*)d_in[8];
    const float* Wn2   = (const float*)d_in[9];
    const float* bn2   = (const float*)d_in[10];
    float* out = (float*)d_out;

    const int N = in_sizes[0] / HDIM;   // 50000
    const int E = in_sizes[1] / 2;      // 800000

    cudaFuncSetAttribute(gnn_h_kernel<0, 384>,
                         cudaFuncAttributeMaxDynamicSharedMemorySize, SMEM_BYTES);
    cudaFuncSetAttribute(gnn_h_kernel<1, 256>,
                         cudaFuncAttributeMaxDynamicSharedMemorySize, SMEM_BYTES);

    void *aggp, *xhp, *w1, *w2, *wn1, *wn2;
    cudaGetSymbolAddress(&aggp, g_agg);
    cudaGetSymbolAddress(&xhp,  g_xh);
    cudaGetSymbolAddress(&w1,   g_W1h);
    cudaGetSymbolAddress(&w2,   g_W2h);
    cudaGetSymbolAddress(&wn1,  g_Wn1h);
    cudaGetSymbolAddress(&wn2,  g_Wn2h);

    cudaMemsetAsync(aggp, 0, (size_t)N * HDIM * sizeof(float), 0);

    prep_all<<<(114688 + 255) / 256, 256>>>(
        (__half*)w1, We1, (__half*)w2, We2, (__half*)wn1, Wn1, (__half*)wn2, Wn2);

    const size_t nx8 = (size_t)N * HDIM / 8;
    conv_h8<<<(unsigned)((nx8 + 255) / 256), 256>>>((__half*)xhp, x, nx8);

    gnn_h_kernel<0, 384><<<(E + 127) / 128, 256, SMEM_BYTES>>>(
        (const __half*)xhp, ei, eattr,
        (const __half*)w1, be1, (const __half*)w2, be2, nullptr, E, E);

    gnn_h_kernel<1, 256><<<(N + 127) / 128, 256, SMEM_BYTES>>>(
        (const __half*)xhp, nullptr, (const float*)aggp,
        (const __half*)wn1, bn1, (const __half*)wn2, bn2, out, N, 0);
}

// round 15
// speedup vs baseline: 1.2136x; 1.1893x over previous
#include <cuda_runtime.h>
#include <cuda_fp16.h>
#include <cstdint>

#define HDIM 128
#define MAX_NODES 50000
#define MAX_EDGES 800000

// ---------------- device scratch ----------------
__device__ float  g_agg [(size_t)MAX_NODES * HDIM];
__device__ __half g_xh  [(size_t)MAX_NODES * HDIM];
__device__ __half g_eh  [(size_t)MAX_EDGES * HDIM];
__device__ __half g_W1h [HDIM * 384];   // edge W1^T [n][k] fp16
__device__ __half g_W2h [HDIM * HDIM];
__device__ __half g_Wn1h[HDIM * 256];
__device__ __half g_Wn2h[HDIM * HDIM];

// ---------------- asm helpers ----------------
__device__ __forceinline__ void ldmat4(uint32_t r[4], uint32_t addr) {
    asm volatile("ldmatrix.sync.aligned.m8n8.x4.shared.b16 {%0,%1,%2,%3}, [%4];"
                 : "=r"(r[0]), "=r"(r[1]), "=r"(r[2]), "=r"(r[3]) : "r"(addr));
}
__device__ __forceinline__ void mma16816(float c[4], const uint32_t a[4],
                                         uint32_t b0, uint32_t b1) {
    asm volatile("mma.sync.aligned.m16n8k16.row.col.f32.f16.f16.f32 "
                 "{%0,%1,%2,%3},{%4,%5,%6,%7},{%8,%9},{%0,%1,%2,%3};"
                 : "+f"(c[0]), "+f"(c[1]), "+f"(c[2]), "+f"(c[3])
                 : "r"(a[0]), "r"(a[1]), "r"(a[2]), "r"(a[3]), "r"(b0), "r"(b1));
}
#define CP16(dst, src) \
    asm volatile("cp.async.ca.shared.global [%0], [%1], 16;" :: "r"(dst), "l"(src))
#define CPCOMMIT() asm volatile("cp.async.commit_group;")
#define CPWAIT1()  asm volatile("cp.async.wait_group 1;")
#define CPWAIT0()  asm volatile("cp.async.wait_group 0;")

// ---------------- smem layout (bytes) ----------------
#define IDXO 98304
#define B1O  99328
#define B2O  99840
#define SMEM_BYTES 100352   // 2 CTAs/SM

// =====================================================================
// EDGE kernel: R10 structure (6-slab ring, depth-3), new coalesced epilogue
// chunks: c0,1 = x[src]; c2,3 = x[dst]; c4,5 = eattr_h; c6,7 = GEMM2
// =====================================================================
__global__ __launch_bounds__(256, 2)
void gnn_edge(const __half* __restrict__ xh,
              const int* __restrict__ ei,
              const __half* __restrict__ eh,
              const __half* __restrict__ W1h, const float* __restrict__ b1,
              const __half* __restrict__ W2h, const float* __restrict__ b2,
              int E)
{
    extern __shared__ char smem[];
    const uint32_t su = (uint32_t)__cvta_generic_to_shared(smem);
    const int tid = threadIdx.x, lane = tid & 31, wid = tid >> 5;
    const int wm = wid >> 1, wn = wid & 1;
    const int base = blockIdx.x * 128;

    int*   sidx = (int*)(smem + IDXO);
    float* b1s  = (float*)(smem + B1O);
    float* b2s  = (float*)(smem + B2O);

    if (tid < 128) {
        b1s[tid] = b1[tid];
        b2s[tid] = b2[tid];
        int e = base + tid; if (e >= E) e = E - 1;
        sidx[tid]       = ei[e];
        sidx[128 + tid] = ei[E + e];
    }
    __syncthreads();

    const int r = tid >> 1, h = tid & 1;
    int lr = base + r; if (lr >= E) lr = E - 1;
    const __half* asrc[3];
    asrc[0] = xh + (size_t)sidx[r] * HDIM;
    asrc[1] = xh + (size_t)sidx[128 + r] * HDIM;
    asrc[2] = eh + (size_t)lr * HDIM;

    const int NCH1 = 6, NTOT = 8;
    const int B2S = 0, HS = 2;
    const int rsw = r & 7;

    auto prefetch1 = [&](int c) {
        const int sa = (2 * c) % 6, sb = (2 * c + 1) % 6;
        {   // weights
            const char* s = (const char*)(W1h + (size_t)r * 384 + c * 64) + h * 64;
            uint32_t d = su + sb * 16384 + r * 128;
            #pragma unroll
            for (int i = 0; i < 4; ++i)
                CP16(d + (((uint32_t)(h * 4 + i) ^ rsw) << 4), s + i * 16);
        }
        {   // A gather
            const char* s = (const char*)(asrc[c >> 1] + (c & 1) * 64) + h * 64;
            uint32_t d = su + sa * 16384 + r * 128;
            #pragma unroll
            for (int i = 0; i < 4; ++i)
                CP16(d + (((uint32_t)(h * 4 + i) ^ rsw) << 4), s + i * 16);
        }
    };
    auto prefetchB2 = [&]() {
        #pragma unroll
        for (int j = 0; j < 2; ++j) {
            const char* s = (const char*)(W2h + (size_t)r * HDIM + j * 64) + h * 64;
            uint32_t d = su + (B2S + j) * 16384 + r * 128;
            #pragma unroll
            for (int i = 0; i < 4; ++i)
                CP16(d + (((uint32_t)(h * 4 + i) ^ rsw) << 4), s + i * 16);
        }
    };

    uint32_t aoff[2], asw[2];
    {
        int ra = wm * 32 + (lane & 15);
        aoff[0] = ra * 128;        asw[0] = ra & 7;
        aoff[1] = (ra + 16) * 128; asw[1] = (ra + 16) & 7;
    }
    const uint32_t aub = lane >> 4;
    uint32_t boff[4], bsw[4];
    {
        int nb0 = wn * 64 + ((lane >> 4) << 3) + (lane & 7);
        #pragma unroll
        for (int p = 0; p < 4; ++p) {
            int nb = nb0 + p * 16;
            boff[p] = nb * 128; bsw[p] = nb & 7;
        }
    }
    const uint32_t bub = (lane >> 3) & 1;

    const int mrow = wm * 32 + (lane >> 2);
    const int ncol = wn * 64 + (lane & 3) * 2;
    float acc[2][8][4];
    #pragma unroll
    for (int mt = 0; mt < 2; ++mt)
        #pragma unroll
        for (int nt = 0; nt < 8; ++nt) {
            int n = ncol + nt * 8;
            acc[mt][nt][0] = b1s[n]; acc[mt][nt][1] = b1s[n + 1];
            acc[mt][nt][2] = b1s[n]; acc[mt][nt][3] = b1s[n + 1];
        }

    prefetch1(0); CPCOMMIT();
    prefetch1(1); CPCOMMIT();

    #pragma unroll 1
    for (int c = 0; c < NTOT; ++c) {
        CPWAIT1();
        __syncthreads();
        {
            const int t = c + 2;
            if (t < NCH1)       { prefetch1(t); CPCOMMIT(); }
            else if (t == NCH1) { prefetchB2(); CPCOMMIT(); }
            else if (c < NTOT - 1) { CPCOMMIT(); }
        }

        if (c == NCH1) {
            #pragma unroll
            for (int mt = 0; mt < 2; ++mt)
                #pragma unroll
                for (int nt = 0; nt < 8; ++nt) {
                    int m = mrow + mt * 16;
                    int n = ncol + nt * 8;
                    int k = n & 63;
                    uint32_t u = (uint32_t)k >> 3;
                    uint32_t bo = (uint32_t)(lane & 3) * 4;
                    __half2 lo = __floats2half2_rn(fmaxf(acc[mt][nt][0], 0.f),
                                                   fmaxf(acc[mt][nt][1], 0.f));
                    __half2 hi = __floats2half2_rn(fmaxf(acc[mt][nt][2], 0.f),
                                                   fmaxf(acc[mt][nt][3], 0.f));
                    char* s0 = smem + (HS + wn) * 16384 + m * 128
                             + ((u ^ (uint32_t)(m & 7)) << 4) + bo;
                    char* s1 = smem + (HS + wn) * 16384 + (m + 8) * 128
                             + ((u ^ (uint32_t)((m + 8) & 7)) << 4) + bo;
                    *(__half2*)s0 = lo;
                    *(__half2*)s1 = hi;
                    acc[mt][nt][0] = b2s[n]; acc[mt][nt][1] = b2s[n + 1];
                    acc[mt][nt][2] = b2s[n]; acc[mt][nt][3] = b2s[n + 1];
                }
            __syncthreads();
        }

        const uint32_t Ab = su + ((c < NCH1) ? ((2 * c) % 6) : (HS + c - NCH1)) * 16384;
        const uint32_t Bb = su + ((c < NCH1) ? ((2 * c + 1) % 6) : (B2S + c - NCH1)) * 16384;
        #pragma unroll
        for (int ks = 0; ks < 4; ++ks) {
            const uint32_t ua = aub + ks * 2;
            const uint32_t ub = bub + ks * 2;
            uint32_t a0[4], a1[4], bf[4][4];
            ldmat4(a0, Ab + aoff[0] + ((ua ^ asw[0]) << 4));
            ldmat4(a1, Ab + aoff[1] + ((ua ^ asw[1]) << 4));
            #pragma unroll
            for (int p = 0; p < 4; ++p)
                ldmat4(bf[p], Bb + boff[p] + ((ub ^ bsw[p]) << 4));
            #pragma unroll
            for (int nt = 0; nt < 8; ++nt) {
                mma16816(acc[0][nt], a0, bf[nt >> 1][(nt & 1) * 2], bf[nt >> 1][(nt & 1) * 2 + 1]);
                mma16816(acc[1][nt], a1, bf[nt >> 1][(nt & 1) * 2], bf[nt >> 1][(nt & 1) * 2 + 1]);
            }
        }
    }
    __syncthreads();

    // ---- epilogue: stage fp32, then warp-per-row coalesced atomic drain ----
    float* stg = (float*)smem;   // [128][132]
    #pragma unroll
    for (int mt = 0; mt < 2; ++mt)
        #pragma unroll
        for (int nt = 0; nt < 8; ++nt) {
            int m = mrow + mt * 16;
            int n = ncol + nt * 8;
            *(float2*)(stg + m * 132 + n)       = make_float2(acc[mt][nt][0], acc[mt][nt][1]);
            *(float2*)(stg + (m + 8) * 132 + n) = make_float2(acc[mt][nt][2], acc[mt][nt][3]);
        }
    __syncthreads();

    #pragma unroll 1
    for (int it = 0; it < 16; ++it) {
        const int row = wid * 16 + it;
        float4 v = *(const float4*)(stg + row * 132 + lane * 4);
        if (base + row < E) {
            const int cd = sidx[128 + row];
            float* dst = g_agg + (size_t)cd * HDIM + lane * 4;
            asm volatile("red.global.add.v4.f32 [%0], {%1,%2,%3,%4};"
                         :: "l"(dst), "f"(v.x), "f"(v.y), "f"(v.z), "f"(v.w)
                         : "memory");
        }
    }
}

// =====================================================================
// NODE kernel: depth-2 double-buffer, agg read fp32 + in-kernel convert
// chunks: c0,1 = x (fp16); c2,3 = agg (fp32 staged); c4,5 = GEMM2
// =====================================================================
#define AOFF 0
#define BOFF 32768
#define HOFF 65536

__global__ __launch_bounds__(256, 2)
void gnn_node(const __half* __restrict__ xh,
              const float* __restrict__ agg,
              const __half* __restrict__ W1h, const float* __restrict__ b1,
              const __half* __restrict__ W2h, const float* __restrict__ b2,
              float* __restrict__ out, int N)
{
    extern __shared__ char smem[];
    const uint32_t su = (uint32_t)__cvta_generic_to_shared(smem);
    const int tid = threadIdx.x, lane = tid & 31, wid = tid >> 5;
    const int wm = wid >> 1, wn = wid & 1;
    const int base = blockIdx.x * 128;

    float* b1s = (float*)(smem + B1O);
    float* b2s = (float*)(smem + B2O);
    if (tid < 128) { b1s[tid] = b1[tid]; b2s[tid] = b2[tid]; }
    __syncthreads();

    const int r = tid >> 1, h = tid & 1;
    int lr = base + r; if (lr >= N) lr = N - 1;
    const __half* xrow = xh + (size_t)lr * HDIM;
    const float*  frow = agg + (size_t)lr * HDIM;
    const int rsw = r & 7;
    const int NCH1 = 4, NTOT = 6, F0 = 2;

    auto prefetch = [&](int c) {
        {   // weights
            const __half* W; int Ks, ko;
            if (c < NCH1) { W = W1h; Ks = 256; ko = c * 64; }
            else          { W = W2h; Ks = HDIM; ko = (c - NCH1) * 64; }
            const char* s = (const char*)(W + (size_t)r * Ks + ko) + h * 64;
            uint32_t d = su + BOFF + (c & 1) * 16384 + r * 128;
            #pragma unroll
            for (int i = 0; i < 4; ++i)
                CP16(d + (((uint32_t)(h * 4 + i) ^ rsw) << 4), s + i * 16);
        }
        if (c < F0) {
            const char* s = (const char*)(xrow + (c & 1) * 64) + h * 64;
            uint32_t d = su + AOFF + (c & 1) * 16384 + r * 128;
            #pragma unroll
            for (int i = 0; i < 4; ++i)
                CP16(d + (((uint32_t)(h * 4 + i) ^ rsw) << 4), s + i * 16);
        } else if (c < NCH1) {
            const char* s = (const char*)(frow + (c & 1) * 64) + h * 128;
            uint32_t d = su + HOFF + r * 256 + h * 128;
            #pragma unroll
            for (int i = 0; i < 8; ++i)
                CP16(d + i * 16, s + i * 16);
        }
    };

    uint32_t aoff[2], asw[2];
    {
        int ra = wm * 32 + (lane & 15);
        aoff[0] = ra * 128;        asw[0] = ra & 7;
        aoff[1] = (ra + 16) * 128; asw[1] = (ra + 16) & 7;
    }
    const uint32_t aub = lane >> 4;
    uint32_t boff[4], bsw[4];
    {
        int nb0 = wn * 64 + ((lane >> 4) << 3) + (lane & 7);
        #pragma unroll
        for (int p = 0; p < 4; ++p) {
            int nb = nb0 + p * 16;
            boff[p] = nb * 128; bsw[p] = nb & 7;
        }
    }
    const uint32_t bub = (lane >> 3) & 1;

    const int mrow = wm * 32 + (lane >> 2);
    const int ncol = wn * 64 + (lane & 3) * 2;
    float acc[2][8][4];
    #pragma unroll
    for (int mt = 0; mt < 2; ++mt)
        #pragma unroll
        for (int nt = 0; nt < 8; ++nt) {
            int n = ncol + nt * 8;
            acc[mt][nt][0] = b1s[n]; acc[mt][nt][1] = b1s[n + 1];
            acc[mt][nt][2] = b1s[n]; acc[mt][nt][3] = b1s[n + 1];
        }

    prefetch(0); CPCOMMIT();

    #pragma unroll 1
    for (int c = 0; c < NTOT; ++c) {
        CPWAIT0();
        __syncthreads();

        if (c >= F0 && c < NCH1) {
            const int slab = (c & 1) * 16384;
            #pragma unroll
            for (int j = 0; j < 8; ++j) {
                float4 v = *(const float4*)(smem + HOFF + j * 4096 + tid * 16);
                int row = j * 16 + wid * 2 + (lane >> 4);
                uint32_t u = ((uint32_t)(lane & 15)) >> 1;
                char* p = smem + AOFF + slab + row * 128
                        + ((u ^ (uint32_t)(row & 7)) << 4) + (lane & 1) * 8;
                ((__half2*)p)[0] = __floats2half2_rn(v.x, v.y);
                ((__half2*)p)[1] = __floats2half2_rn(v.z, v.w);
            }
            __syncthreads();
        }

        if (c + 1 < NTOT) { prefetch(c + 1); CPCOMMIT(); }

        if (c == NCH1) {
            #pragma unroll
            for (int mt = 0; mt < 2; ++mt)
                #pragma unroll
                for (int nt = 0; nt < 8; ++nt) {
                    int m = mrow + mt * 16;
                    int n = ncol + nt * 8;
                    int k = n & 63;
                    uint32_t u = (uint32_t)k >> 3;
                    uint32_t bo = (uint32_t)(lane & 3) * 4;
                    __half2 lo = __floats2half2_rn(fmaxf(acc[mt][nt][0], 0.f),
                                                   fmaxf(acc[mt][nt][1], 0.f));
                    __half2 hi = __floats2half2_rn(fmaxf(acc[mt][nt][2], 0.f),
                                                   fmaxf(acc[mt][nt][3], 0.f));
                    char* s0 = smem + HOFF + wn * 16384 + m * 128
                             + ((u ^ (uint32_t)(m & 7)) << 4) + bo;
                    char* s1 = smem + HOFF + wn * 16384 + (m + 8) * 128
                             + ((u ^ (uint32_t)((m + 8) & 7)) << 4) + bo;
                    *(__half2*)s0 = lo;
                    *(__half2*)s1 = hi;
                    acc[mt][nt][0] = b2s[n]; acc[mt][nt][1] = b2s[n + 1];
                    acc[mt][nt][2] = b2s[n]; acc[mt][nt][3] = b2s[n + 1];
                }
            __syncthreads();
        }

        const uint32_t Ab = (c < NCH1) ? (su + AOFF + (c & 1) * 16384)
                                       : (su + HOFF + (c - NCH1) * 16384);
        const uint32_t Bb = su + BOFF + (c & 1) * 16384;
        #pragma unroll
        for (int ks = 0; ks < 4; ++ks) {
            const uint32_t ua = aub + ks * 2;
            const uint32_t ub = bub + ks * 2;
            uint32_t a0[4], a1[4], bf[4][4];
            ldmat4(a0, Ab + aoff[0] + ((ua ^ asw[0]) << 4));
            ldmat4(a1, Ab + aoff[1] + ((ua ^ asw[1]) << 4));
            #pragma unroll
            for (int p = 0; p < 4; ++p)
                ldmat4(bf[p], Bb + boff[p] + ((ub ^ bsw[p]) << 4));
            #pragma unroll
            for (int nt = 0; nt < 8; ++nt) {
                mma16816(acc[0][nt], a0, bf[nt >> 1][(nt & 1) * 2], bf[nt >> 1][(nt & 1) * 2 + 1]);
                mma16816(acc[1][nt], a1, bf[nt >> 1][(nt & 1) * 2], bf[nt >> 1][(nt & 1) * 2 + 1]);
            }
        }
        __syncthreads();
    }

    // ---- epilogue: stage fp32, warp-per-row coalesced stores ----
    float* stg = (float*)smem;
    #pragma unroll
    for (int mt = 0; mt < 2; ++mt)
        #pragma unroll
        for (int nt = 0; nt < 8; ++nt) {
            int m = mrow + mt * 16;
            int n = ncol + nt * 8;
            *(float2*)(stg + m * 132 + n)       = make_float2(acc[mt][nt][0], acc[mt][nt][1]);
            *(float2*)(stg + (m + 8) * 132 + n) = make_float2(acc[mt][nt][2], acc[mt][nt][3]);
        }
    __syncthreads();

    #pragma unroll 1
    for (int it = 0; it < 16; ++it) {
        const int row = wid * 16 + it;
        float4 v = *(const float4*)(stg + row * 132 + lane * 4);
        if (base + row < N)
            *(float4*)(out + (size_t)(base + row) * HDIM + lane * 4) = v;
    }
}

// fused weight prep: transpose + fp16 for all 4 matrices
__global__ void prep_all(__half* w1, const float* We1,
                         __half* w2, const float* We2,
                         __half* wn1, const float* Wn1,
                         __half* wn2, const float* Wn2)
{
    int i = blockIdx.x * 256 + threadIdx.x;
    const float* src; __half* dst; int K, j;
    if (i < 49152)      { src = We1; dst = w1;  K = 384; j = i; }
    else if (i < 65536) { src = We2; dst = w2;  K = 128; j = i - 49152; }
    else if (i < 98304) { src = Wn1; dst = wn1; K = 256; j = i - 65536; }
    else if (i < 114688){ src = Wn2; dst = wn2; K = 128; j = i - 98304; }
    else return;
    int k = j / HDIM, n = j % HDIM;
    dst[(size_t)n * K + k] = __float2half(src[(size_t)k * HDIM + n]);
}
// fused fp32->fp16 for x then eattr, 8 elems/thread
__global__ void conv_h8_2(__half* __restrict__ d0, const float* __restrict__ s0,
                          size_t n8_0,
                          __half* __restrict__ d1, const float* __restrict__ s1,
                          size_t n8_1) {
    size_t i = (size_t)blockIdx.x * 256 + threadIdx.x;
    const float* src; __half* dst; size_t j;
    if (i < n8_0)            { src = s0; dst = d0; j = i; }
    else if (i < n8_0 + n8_1){ src = s1; dst = d1; j = i - n8_0; }
    else return;
    float4 v0 = ((const float4*)src)[j * 2];
    float4 v1 = ((const float4*)src)[j * 2 + 1];
    __half2 hh[4] = { __floats2half2_rn(v0.x, v0.y), __floats2half2_rn(v0.z, v0.w),
                      __floats2half2_rn(v1.x, v1.y), __floats2half2_rn(v1.z, v1.w) };
    *(uint4*)(dst + j * 8) = *(const uint4*)hh;
}

extern "C" void kernel_launch(void* const* d_in, const int* in_sizes, int n_in,
                              void* d_out, int out_size)
{
    const float* x     = (const float*)d_in[0];
    const int*   ei    = (const int*)d_in[1];
    const float* eattr = (const float*)d_in[2];
    const float* We1   = (const float*)d_in[3];
    const float* be1   = (const float*)d_in[4];
    const float* We2   = (const float*)d_in[5];
    const float* be2   = (const float*)d_in[6];
    const float* Wn1   = (const float*)d_in[7];
    const float* bn1   = (const float*)d_in[8];
    const float* Wn2   = (const float*)d_in[9];
    const float* bn2   = (const float*)d_in[10];
    float* out = (float*)d_out;

    const int N = in_sizes[0] / HDIM;   // 50000
    const int E = in_sizes[1] / 2;      // 800000

    cudaFuncSetAttribute(gnn_edge, cudaFuncAttributeMaxDynamicSharedMemorySize, SMEM_BYTES);
    cudaFuncSetAttribute(gnn_node, cudaFuncAttributeMaxDynamicSharedMemorySize, SMEM_BYTES);

    void *aggp, *xhp, *ehp, *w1, *w2, *wn1, *wn2;
    cudaGetSymbolAddress(&aggp, g_agg);
    cudaGetSymbolAddress(&xhp,  g_xh);
    cudaGetSymbolAddress(&ehp,  g_eh);
    cudaGetSymbolAddress(&w1,   g_W1h);
    cudaGetSymbolAddress(&w2,   g_W2h);
    cudaGetSymbolAddress(&wn1,  g_Wn1h);
    cudaGetSymbolAddress(&wn2,  g_Wn2h);

    cudaMemsetAsync(aggp, 0, (size_t)N * HDIM * sizeof(float), 0);

    prep_all<<<(114688 + 255) / 256, 256>>>(
        (__half*)w1, We1, (__half*)w2, We2, (__half*)wn1, Wn1, (__half*)wn2, Wn2);

    const size_t nx8 = (size_t)N * HDIM / 8;
    const size_t ne8 = (size_t)E * HDIM / 8;
    conv_h8_2<<<(unsigned)((nx8 + ne8 + 255) / 256), 256>>>(
        (__half*)xhp, x, nx8, (__half*)ehp, eattr, ne8);

    gnn_edge<<<(E + 127) / 128, 256, SMEM_BYTES>>>(
        (const __half*)xhp, ei, (const __half*)ehp,
        (const __half*)w1, be1, (const __half*)w2, be2, E);

    gnn_node<<<(N + 127) / 128, 256, SMEM_BYTES>>>(
        (const __half*)xhp, (const float*)aggp,
        (const __half*)wn1, bn1, (const __half*)wn2, bn2, out, N);
}